// round 7
// baseline (speedup 1.0000x reference)
#include <cuda_runtime.h>
#include <cuda_bf16.h>
#include <cuda_fp16.h>
#include <cstdint>

// Problem constants
#define BATCH 8
#define NNODE 2048
#define DIM   256
#define MROWS (BATCH * NNODE)   // 16384

// -------------------- scratch (no allocations allowed) --------------------
__device__ float g_H[(size_t)MROWS * DIM];          // 16 MB fp32 (sproj)
__device__ __half g_Hh[(size_t)MROWS * DIM];        // 8 MB fp16 (gather)
__device__ float g_s1[MROWS];
__device__ float g_s2[MROWS];
__device__ __nv_bfloat16 g_Xhi[(size_t)MROWS * DIM];
__device__ __nv_bfloat16 g_Xlo[(size_t)MROWS * DIM];
__device__ __nv_bfloat16 g_Whi[DIM * DIM];
__device__ __nv_bfloat16 g_Wlo[DIM * DIM];

// ============================================================================
// Helpers (base sm_103 target: ldmatrix + mma.sync + cp.async; NO tcgen05)
// ============================================================================
__device__ __forceinline__ uint32_t smem_u32(const void* p) {
    uint32_t a;
    asm("{ .reg .u64 t; cvta.to.shared.u64 t, %1; cvt.u32.u64 %0, t; }"
        : "=r"(a) : "l"(p));
    return a;
}

__device__ __forceinline__ void cp16(uint32_t dst, const void* src) {
    asm volatile("cp.async.cg.shared.global [%0], [%1], 16;"
                 :: "r"(dst), "l"(src));
}
#define CP_COMMIT() asm volatile("cp.async.commit_group;" ::: "memory")
#define CP_WAIT0()  asm volatile("cp.async.wait_group 0;" ::: "memory")

__device__ __forceinline__ void ldm_x4(uint32_t* r, uint32_t addr) {
    asm volatile("ldmatrix.sync.aligned.m8n8.x4.shared.b16 {%0,%1,%2,%3}, [%4];"
        : "=r"(r[0]), "=r"(r[1]), "=r"(r[2]), "=r"(r[3]) : "r"(addr));
}

__device__ __forceinline__ void mma_bf16(float* c, const uint32_t* a,
                                         const uint32_t* b) {
    asm volatile(
        "mma.sync.aligned.m16n8k16.row.col.f32.bf16.bf16.f32 "
        "{%0,%1,%2,%3}, {%4,%5,%6,%7}, {%8,%9}, {%0,%1,%2,%3};"
        : "+f"(c[0]), "+f"(c[1]), "+f"(c[2]), "+f"(c[3])
        : "r"(a[0]), "r"(a[1]), "r"(a[2]), "r"(a[3]), "r"(b[0]), "r"(b[1]));
}

// bf16 split: hi = bf16(x), lo = bf16(x - hi); packs (e0, e1) pairs.
__device__ __forceinline__ void split_pair(float e0, float e1,
                                           uint32_t& h, uint32_t& l) {
    asm("cvt.rn.bf16x2.f32 %0, %1, %2;" : "=r"(h) : "f"(e1), "f"(e0));
    __nv_bfloat162 hb = *(__nv_bfloat162*)&h;
    float r0 = e0 - __bfloat162float(hb.x);
    float r1 = e1 - __bfloat162float(hb.y);
    asm("cvt.rn.bf16x2.f32 %0, %1, %2;" : "=r"(l) : "f"(r1), "f"(r0));
}

// ============================================================================
// Kernel 0: fp32 -> split-bf16 conversion
// ============================================================================
__global__ void __launch_bounds__(256)
convert_split(const float* __restrict__ src, __nv_bfloat16* __restrict__ hi,
              __nv_bfloat16* __restrict__ lo)
{
    const int idx = blockIdx.x * 256 + threadIdx.x;
    const float* s = src + (size_t)idx * 8;
    float4 v0 = *(const float4*)(s);
    float4 v1 = *(const float4*)(s + 4);
    uint32_t h[4], l[4];
    split_pair(v0.x, v0.y, h[0], l[0]);
    split_pair(v0.z, v0.w, h[1], l[1]);
    split_pair(v1.x, v1.y, h[2], l[2]);
    split_pair(v1.z, v1.w, h[3], l[3]);
    uint4* hp = (uint4*)(hi + (size_t)idx * 8);
    uint4* lp = (uint4*)(lo + (size_t)idx * 8);
    *hp = make_uint4(h[0], h[1], h[2], h[3]);
    *lp = make_uint4(l[0], l[1], l[2], l[3]);
}

// ============================================================================
// Kernel 1: split-bf16 HMMA GEMM  H[m,d] = sum_k X[m,k]*W[d,k] + b[d]
// CTA 128x128, 8 warps, warp tile 64x32, K-step 16, 2-stage cp.async.
// Epilogue writes fp32 H (for sproj) AND fp16 H (for the gather).
// ============================================================================
#define SROW 24
#define STAGE_B (128 * SROW * 2)

__global__ void __launch_bounds__(256, 1)
gemm_h_mma(const __nv_bfloat16* __restrict__ Xhi,
           const __nv_bfloat16* __restrict__ Xlo,
           const __nv_bfloat16* __restrict__ Whi,
           const __nv_bfloat16* __restrict__ Wlo,
           const float* __restrict__ bias)
{
    __shared__ __nv_bfloat16 sAhi[2][128][SROW];
    __shared__ __nv_bfloat16 sAlo[2][128][SROW];
    __shared__ __nv_bfloat16 sBhi[2][128][SROW];
    __shared__ __nv_bfloat16 sBlo[2][128][SROW];

    const int tid   = threadIdx.x;
    const int wid   = tid >> 5;
    const int lane  = tid & 31;
    const int cta_m = blockIdx.x * 128;
    const int cta_n = blockIdx.y * 128;

    const int wm = (wid & 1) * 64;
    const int wn = (wid >> 1) * 32;

    const int lrow  = tid >> 1;
    const int lhalf = (tid & 1) * 8;
    const __nv_bfloat16* srcAhi = Xhi + (size_t)(cta_m + lrow) * DIM + lhalf;
    const __nv_bfloat16* srcAlo = Xlo + (size_t)(cta_m + lrow) * DIM + lhalf;
    const __nv_bfloat16* srcBhi = Whi + (size_t)(cta_n + lrow) * DIM + lhalf;
    const __nv_bfloat16* srcBlo = Wlo + (size_t)(cta_n + lrow) * DIM + lhalf;
    const uint32_t dAhi = smem_u32(&sAhi[0][lrow][lhalf]);
    const uint32_t dAlo = smem_u32(&sAlo[0][lrow][lhalf]);
    const uint32_t dBhi = smem_u32(&sBhi[0][lrow][lhalf]);
    const uint32_t dBlo = smem_u32(&sBlo[0][lrow][lhalf]);

    uint32_t aAhi[4], aAlo[4];
#pragma unroll
    for (int mt = 0; mt < 4; mt++) {
        int row = wm + mt * 16 + (lane & 15);
        int kh  = (lane >> 4) * 8;
        aAhi[mt] = smem_u32(&sAhi[0][row][kh]);
        aAlo[mt] = smem_u32(&sAlo[0][row][kh]);
    }
    uint32_t bBhi[2], bBlo[2];
#pragma unroll
    for (int nt2 = 0; nt2 < 2; nt2++) {
        int nr = wn + nt2 * 16 + ((lane >> 4) * 8) + (lane & 7);
        int kh = ((lane >> 3) & 1) * 8;
        bBhi[nt2] = smem_u32(&sBhi[0][nr][kh]);
        bBlo[nt2] = smem_u32(&sBlo[0][nr][kh]);
    }

    float acc[4][4][4];
#pragma unroll
    for (int mt = 0; mt < 4; mt++)
#pragma unroll
        for (int nt = 0; nt < 4; nt++)
#pragma unroll
            for (int c = 0; c < 4; c++) acc[mt][nt][c] = 0.f;

    cp16(dAhi, srcAhi); cp16(dAlo, srcAlo);
    cp16(dBhi, srcBhi); cp16(dBlo, srcBlo);
    CP_COMMIT();

#pragma unroll 1
    for (int ks = 0; ks < DIM / 16; ks++) {
        CP_WAIT0();
        __syncthreads();

        if (ks + 1 < DIM / 16) {
            const uint32_t so = (uint32_t)(((ks + 1) & 1) * STAGE_B);
            const int ko = (ks + 1) * 16;
            cp16(dAhi + so, srcAhi + ko); cp16(dAlo + so, srcAlo + ko);
            cp16(dBhi + so, srcBhi + ko); cp16(dBlo + so, srcBlo + ko);
        }
        CP_COMMIT();

        const uint32_t st = (uint32_t)((ks & 1) * STAGE_B);

        uint32_t fAhi[4][4], fAlo[4][4];
#pragma unroll
        for (int mt = 0; mt < 4; mt++) {
            ldm_x4(fAhi[mt], aAhi[mt] + st);
            ldm_x4(fAlo[mt], aAlo[mt] + st);
        }
        uint32_t fBhi[4][2], fBlo[4][2];
#pragma unroll
        for (int nt2 = 0; nt2 < 2; nt2++) {
            uint32_t r[4];
            ldm_x4(r, bBhi[nt2] + st);
            fBhi[nt2 * 2][0] = r[0]; fBhi[nt2 * 2][1] = r[1];
            fBhi[nt2 * 2 + 1][0] = r[2]; fBhi[nt2 * 2 + 1][1] = r[3];
            ldm_x4(r, bBlo[nt2] + st);
            fBlo[nt2 * 2][0] = r[0]; fBlo[nt2 * 2][1] = r[1];
            fBlo[nt2 * 2 + 1][0] = r[2]; fBlo[nt2 * 2 + 1][1] = r[3];
        }

#pragma unroll
        for (int mt = 0; mt < 4; mt++)
#pragma unroll
            for (int nt = 0; nt < 4; nt++) {
                mma_bf16(acc[mt][nt], fAhi[mt], fBhi[nt]);
                mma_bf16(acc[mt][nt], fAhi[mt], fBlo[nt]);
                mma_bf16(acc[mt][nt], fAlo[mt], fBhi[nt]);
            }
    }

    // ---- epilogue: +bias, store fp32 H and fp16 H ----
    const int gid = lane >> 2;
    const int tig = lane & 3;
#pragma unroll
    for (int nt = 0; nt < 4; nt++) {
        const int col = cta_n + wn + nt * 8 + tig * 2;
        const float2 bv = *(const float2*)(bias + col);
#pragma unroll
        for (int mt = 0; mt < 4; mt++) {
            const int m0 = cta_m + wm + mt * 16 + gid;
            float2 v0 = make_float2(acc[mt][nt][0] + bv.x, acc[mt][nt][1] + bv.y);
            float2 v1 = make_float2(acc[mt][nt][2] + bv.x, acc[mt][nt][3] + bv.y);
            *(float2*)(g_H + (size_t)m0 * DIM + col)       = v0;
            *(float2*)(g_H + (size_t)(m0 + 8) * DIM + col) = v1;
            *(__half2*)(g_Hh + (size_t)m0 * DIM + col)       = __float22half2_rn(v0);
            *(__half2*)(g_Hh + (size_t)(m0 + 8) * DIM + col) = __float22half2_rn(v1);
        }
    }
}

// ============================================================================
// Kernel 2: s1[r] = h[r,:]@a1 + att_b ; s2[r] = h[r,:]@a2  (float4 ILP)
// ============================================================================
__global__ void __launch_bounds__(256)
sproj_kernel(const float* __restrict__ a1, const float* __restrict__ a2,
             const float* __restrict__ att_b)
{
    const int row  = blockIdx.x * 8 + (threadIdx.x >> 5);
    const int lane = threadIdx.x & 31;
    const float* hr = g_H + (size_t)row * DIM + lane * 8;

    float4 h0 = *(const float4*)(hr);
    float4 h1 = *(const float4*)(hr + 4);
    float4 p0 = *(const float4*)(a1 + lane * 8);
    float4 p1 = *(const float4*)(a1 + lane * 8 + 4);
    float4 q0 = *(const float4*)(a2 + lane * 8);
    float4 q1 = *(const float4*)(a2 + lane * 8 + 4);

    float d1 = h0.x * p0.x + h0.y * p0.y + h0.z * p0.z + h0.w * p0.w
             + h1.x * p1.x + h1.y * p1.y + h1.z * p1.z + h1.w * p1.w;
    float d2 = h0.x * q0.x + h0.y * q0.y + h0.z * q0.z + h0.w * q0.w
             + h1.x * q1.x + h1.y * q1.y + h1.z * q1.z + h1.w * q1.w;

#pragma unroll
    for (int o = 16; o; o >>= 1) {
        d1 += __shfl_xor_sync(0xffffffffu, d1, o);
        d2 += __shfl_xor_sync(0xffffffffu, d2, o);
    }
    if (lane == 0) {
        g_s1[row] = d1 + att_b[0];
        g_s2[row] = d2;
    }
}

// ============================================================================
// Kernel 3: per-node attention + sparse aggregation.
// Phase B now gathers fp16 H rows (half the L2 bytes).
// ============================================================================
__global__ void __launch_bounds__(256)
attn_agg_kernel(const float* __restrict__ adj, const float* __restrict__ mask,
                float* __restrict__ out)
{
    const int i   = blockIdx.x;
    const int b   = blockIdx.y;
    const int tid = threadIdx.x;
    const int row = b * NNODE + i;

    __shared__ float wbuf[NNODE];
    __shared__ int   jbuf[NNODE];
    __shared__ float sred[4][DIM];
    __shared__ int   s_cnt;
    __shared__ float s_sum;

    const float mi = mask[row];
    float* orow = out + (size_t)row * DIM;
    if (mi == 0.f) {
        orow[tid] = 0.f;
        return;
    }

    if (tid == 0) { s_cnt = 0; s_sum = 0.f; }
    __syncthreads();

    const float* arow = adj + (size_t)row * NNODE;
    const float  s1i  = g_s1[row];
    const float* mrow = mask + b * NNODE;
    const float* s2b  = g_s2 + b * NNODE;
    const int lane = tid & 31;

    float4 av[2], mv[2], sv[2];
#pragma unroll
    for (int u = 0; u < 2; u++) {
        int j0 = tid * 4 + u * 1024;
        av[u] = *(const float4*)(arow + j0);
        mv[u] = *(const float4*)(mrow + j0);
        sv[u] = *(const float4*)(s2b + j0);
    }

    float w[8];
    float psum = 0.f;
#pragma unroll
    for (int u = 0; u < 2; u++) {
        const float* ap = (const float*)&av[u];
        const float* mp = (const float*)&mv[u];
        const float* sp = (const float*)&sv[u];
#pragma unroll
        for (int e = 0; e < 4; e++) {
            float ww = 0.f;
            if (ap[e] != 0.f && mp[e] != 0.f) {
                float lg = s1i + sp[e];
                ww = ap[e] * mp[e] / (1.f + __expf(-lg));
            }
            w[u * 4 + e] = ww;
            psum += ww;
        }
    }

#pragma unroll
    for (int e = 0; e < 8; e++) {
        unsigned bal = __ballot_sync(0xffffffffu, w[e] != 0.f);
        if (bal) {
            int leader = __ffs(bal) - 1;
            int base = 0;
            if (lane == leader) base = atomicAdd(&s_cnt, __popc(bal));
            base = __shfl_sync(0xffffffffu, base, leader);
            if (w[e] != 0.f) {
                int rank = __popc(bal & ((1u << lane) - 1u));
                wbuf[base + rank] = w[e];
                jbuf[base + rank] = tid * 4 + (e >> 2) * 1024 + (e & 3);
            }
        }
    }

#pragma unroll
    for (int o = 16; o; o >>= 1) psum += __shfl_xor_sync(0xffffffffu, psum, o);
    if (lane == 0) atomicAdd(&s_sum, psum);
    __syncthreads();

    const int n   = s_cnt;
    const float inv = 1.f / (s_sum + 1e-8f);
    const __half* Hb = g_Hh + (size_t)b * NNODE * DIM;

    const int g  = tid >> 6;             // neighbor group 0..3
    const int c4 = (tid & 63) * 4;       // channel quad

    float4 acc = make_float4(0.f, 0.f, 0.f, 0.f);
    int k = g;
    for (; k + 4 < n; k += 8) {          // two neighbors per iter
        int   ja = jbuf[k],   jc = jbuf[k + 4];
        float wa = wbuf[k],   wc = wbuf[k + 4];
        uint2 ra = *(const uint2*)(Hb + (size_t)ja * DIM + c4);
        uint2 rc = *(const uint2*)(Hb + (size_t)jc * DIM + c4);
        float2 a0 = __half22float2(*(__half2*)&ra.x);
        float2 a1f = __half22float2(*(__half2*)&ra.y);
        float2 c0 = __half22float2(*(__half2*)&rc.x);
        float2 c1 = __half22float2(*(__half2*)&rc.y);
        acc.x += wa * a0.x  + wc * c0.x;
        acc.y += wa * a0.y  + wc * c0.y;
        acc.z += wa * a1f.x + wc * c1.x;
        acc.w += wa * a1f.y + wc * c1.y;
    }
    if (k < n) {
        int   ja = jbuf[k];
        float wa = wbuf[k];
        uint2 ra = *(const uint2*)(Hb + (size_t)ja * DIM + c4);
        float2 a0 = __half22float2(*(__half2*)&ra.x);
        float2 a1f = __half22float2(*(__half2*)&ra.y);
        acc.x += wa * a0.x;  acc.y += wa * a0.y;
        acc.z += wa * a1f.x; acc.w += wa * a1f.y;
    }

    *(float4*)&sred[g][c4] = acc;
    __syncthreads();

    float r = sred[0][tid] + sred[1][tid] + sred[2][tid] + sred[3][tid];
    orow[tid] = r * inv;
}

// ============================================================================
// Launch
// ============================================================================
extern "C" void kernel_launch(void* const* d_in, const int* in_sizes, int n_in,
                              void* d_out, int out_size)
{
    const float* x     = (const float*)d_in[0];
    const float* adj   = (const float*)d_in[1];
    const float* mask  = (const float*)d_in[2];
    const float* W     = (const float*)d_in[3];
    const float* bias  = (const float*)d_in[4];
    const float* a1    = (const float*)d_in[5];
    const float* a2    = (const float*)d_in[6];
    const float* att_b = (const float*)d_in[7];
    float* out = (float*)d_out;

    __nv_bfloat16 *xhi, *xlo, *whi, *wlo;
    cudaGetSymbolAddress((void**)&xhi, g_Xhi);
    cudaGetSymbolAddress((void**)&xlo, g_Xlo);
    cudaGetSymbolAddress((void**)&whi, g_Whi);
    cudaGetSymbolAddress((void**)&wlo, g_Wlo);

    convert_split<<<(MROWS * DIM) / (256 * 8), 256>>>(x, xhi, xlo);
    convert_split<<<(DIM * DIM) / (256 * 8), 256>>>(W, whi, wlo);

    dim3 g1(MROWS / 128, DIM / 128);      // (128, 2)
    gemm_h_mma<<<g1, 256>>>(xhi, xlo, whi, wlo, bias);

    sproj_kernel<<<MROWS / 8, 256>>>(a1, a2, att_b);

    dim3 g3(NNODE, BATCH);                // (2048, 8)
    attn_agg_kernel<<<g3, 256>>>(adj, mask, out);
}